// round 3
// baseline (speedup 1.0000x reference)
#include <cuda_runtime.h>

#define EPSF 1e-6f
#define S 32
#define C 3
#define K 2          // tiles per warp, packed into f32x2 lanes
#define TILE (S * S) // 1024
#define WARPS_PER_CTA 4

// Precomputed Thomas factorizations: (invd = 1/denom, w = cs*invd).
// c_star = -w, so backward sweep is x_i = d_i + w_i * x_{i+1}.
// Layout: [timeIdx][c][pos_i][row_r] -> warp (lane=r) loads 32 consecutive float2.
__device__ float2 g_xcoef[6 * C * TILE];
__device__ float2 g_ycoef[5 * C * TILE];

// ---------------------------------------------------------------------------
// packed f32x2 helpers (ptxas never auto-fuses these; PTX-only path)
// ---------------------------------------------------------------------------
__device__ __forceinline__ float2 fma2(float2 a, float2 b, float2 c) {
    unsigned long long au = *reinterpret_cast<unsigned long long*>(&a);
    unsigned long long bu = *reinterpret_cast<unsigned long long*>(&b);
    unsigned long long cu = *reinterpret_cast<unsigned long long*>(&c);
    unsigned long long du;
    asm("fma.rn.f32x2 %0, %1, %2, %3;" : "=l"(du) : "l"(au), "l"(bu), "l"(cu));
    return *reinterpret_cast<float2*>(&du);
}
__device__ __forceinline__ float2 mul2(float2 a, float2 b) {
    unsigned long long au = *reinterpret_cast<unsigned long long*>(&a);
    unsigned long long bu = *reinterpret_cast<unsigned long long*>(&b);
    unsigned long long du;
    asm("mul.rn.f32x2 %0, %1, %2;" : "=l"(du) : "l"(au), "l"(bu));
    return *reinterpret_cast<float2*>(&du);
}

// ---------------------------------------------------------------------------
// Precompute kernel: one thread per (timeIdx, c, row). 11*3*32 = 1056 threads.
// ---------------------------------------------------------------------------
__global__ void precompute_kernel(const float* __restrict__ ab,
                                  const float* __restrict__ bb,
                                  const float* __restrict__ atc,
                                  const float* __restrict__ btc) {
    int tid = blockIdx.x * blockDim.x + threadIdx.x;
    if (tid >= 11 * C * S) return;
    int j   = tid / (C * S);
    int rem = tid % (C * S);
    int c   = rem / S;
    int r   = rem % S;

    float t, fac;
    const float* bp;
    const float* tp;
    int stride;
    float2* out;
    if (j < 6) {                       // x-direction, t = j*DT, dt = DT/2
        t   = (float)(j * 0.1);
        fac = 0.05f;
        bp  = ab + (c * S + r) * S;
        tp  = atc + (c * S + r) * S;
        stride = 1;
        out = g_xcoef + (j * C + c) * TILE;
    } else {                           // y-direction, t = DT/2 + jy*DT, dt = DT
        int jy = j - 6;
        t   = (float)(0.05 + jy * 0.1);
        fac = 0.1f;
        bp  = bb + c * TILE + r;
        tp  = btc + c * TILE + r;
        stride = S;
        out = g_ycoef + (jy * C + c) * TILE;
    }

    float coef[S];
#pragma unroll
    for (int i = 0; i < S; ++i)
        coef[i] = fmaxf(bp[i * stride] + t * tp[i * stride], EPSF);

    float cs[S];
    cs[0] = (coef[0] + coef[0] + coef[1]) / 3.0f * fac;
#pragma unroll
    for (int i = 1; i < S - 1; ++i)
        cs[i] = (coef[i - 1] + coef[i] + coef[i + 1]) / 3.0f * fac;
    cs[S - 1] = (coef[S - 2] + coef[S - 1] + coef[S - 1]) / 3.0f * fac;

    float wprev = 0.0f;
#pragma unroll
    for (int i = 0; i < S; ++i) {
        float b = 1.0f + 2.0f * cs[i];
        if (i == 0)     b = 1.0f + cs[0];
        if (i == S - 1) b = 1.0f + cs[S - 1];
        float denom = b - cs[i] * wprev + EPSF;
        float invd  = 1.0f / denom;
        float w     = cs[i] * invd;
        out[i * S + r] = make_float2(invd, w);
        wprev = w;
    }
}

// ---------------------------------------------------------------------------
// Main fused ADI kernel: 4 warps/CTA, each warp owns K=2 tiles packed in f32x2.
// v[i] = (tile0 elem, tile1 elem) for row `lane`, position i.
// ---------------------------------------------------------------------------
__global__ __launch_bounds__(32 * WARPS_PER_CTA)
void adi_kernel(const float* __restrict__ uin, float* __restrict__ uout) {
    __shared__ float smbuf[WARPS_PER_CTA * S * 33];
    const int lane = threadIdx.x & 31;
    const int wip  = threadIdx.x >> 5;
    float* sm = smbuf + wip * (S * 33);

    const int gw  = blockIdx.x * WARPS_PER_CTA + wip;   // global warp id
    const int c   = gw % C;
    const int bg  = gw / C;
    const int base0 = (bg * K) * C * TILE + c * TILE;   // tile k at base0 + k*C*TILE

    float2 v[S];     // packed across the 2 tiles
    float  warr[S];

    // ---- load: gmem (coalesced) -> smem -> regs (lane = row h) ----
#pragma unroll
    for (int k = 0; k < K; ++k) {
        const int tb = base0 + k * C * TILE;
        __syncwarp();
#pragma unroll
        for (int r = 0; r < S; ++r)
            sm[r * 33 + lane] = uin[tb + r * S + lane];
        __syncwarp();
        if (k == 0) {
#pragma unroll
            for (int i = 0; i < S; ++i) v[i].x = sm[lane * 33 + i];
        } else {
#pragma unroll
            for (int i = 0; i < S; ++i) v[i].y = sm[lane * 33 + i];
        }
    }
    __syncwarp();

    // ---- Thomas solve (forward + backward), both tiles per fma via f32x2 ----
    auto solve = [&](const float2* __restrict__ cf) {
        float2 dprev = make_float2(0.0f, 0.0f);
#pragma unroll
        for (int i = 0; i < S; ++i) {
            float2 iw = __ldg(&cf[i * S + lane]);
            warr[i] = iw.y;
            float2 invp = make_float2(iw.x, iw.x);
            float2 wp   = make_float2(iw.y, iw.y);
            float2 t = mul2(v[i], invp);      // independent of chain
            t = fma2(wp, dprev, t);           // 4-cycle recurrence
            v[i] = t;
            dprev = t;
        }
#pragma unroll
        for (int i = S - 2; i >= 0; --i) {
            float2 wp = make_float2(warr[i], warr[i]);
            v[i] = fma2(wp, v[i + 1], v[i]);
        }
    };

    // ---- 32x32 transpose via padded smem, one component at a time ----
    auto transpose = [&]() {
        __syncwarp();
#pragma unroll
        for (int i = 0; i < S; ++i) sm[lane * 33 + i] = v[i].x;
        __syncwarp();
#pragma unroll
        for (int i = 0; i < S; ++i) v[i].x = sm[i * 33 + lane];
        __syncwarp();
#pragma unroll
        for (int i = 0; i < S; ++i) sm[lane * 33 + i] = v[i].y;
        __syncwarp();
#pragma unroll
        for (int i = 0; i < S; ++i) v[i].y = sm[i * 33 + lane];
        __syncwarp();
    };

    const float2* xc = g_xcoef + c * TILE;
    const float2* yc = g_ycoef + c * TILE;

    // substep sequence: X0 | [T Y_it T X_{it+1} (X_{it+1} again if it<4)]
    solve(xc);
#pragma unroll 1
    for (int it = 0; it < 5; ++it) {
        transpose();
        solve(yc + it * C * TILE);
        transpose();
        const float2* cfx = xc + (it + 1) * C * TILE;
        const int reps = (it < 4) ? 2 : 1;
#pragma unroll 1
        for (int rr = 0; rr < reps; ++rr) solve(cfx);
    }

    // ---- store: regs -> smem -> gmem (coalesced) ----
#pragma unroll
    for (int k = 0; k < K; ++k) {
        const int tb = base0 + k * C * TILE;
        __syncwarp();
        if (k == 0) {
#pragma unroll
            for (int i = 0; i < S; ++i) sm[lane * 33 + i] = v[i].x;
        } else {
#pragma unroll
            for (int i = 0; i < S; ++i) sm[lane * 33 + i] = v[i].y;
        }
        __syncwarp();
#pragma unroll
        for (int r = 0; r < S; ++r)
            uout[tb + r * S + lane] = sm[r * 33 + lane];
    }
}

// ---------------------------------------------------------------------------
extern "C" void kernel_launch(void* const* d_in, const int* in_sizes, int n_in,
                              void* d_out, int out_size) {
    const float* u   = (const float*)d_in[0];
    const float* ab  = (const float*)d_in[1];
    const float* bb  = (const float*)d_in[2];
    const float* atc = (const float*)d_in[3];
    const float* btc = (const float*)d_in[4];
    float* out = (float*)d_out;

    const int B = in_sizes[0] / (C * TILE);         // 2048

    precompute_kernel<<<(11 * C * S + 127) / 128, 128>>>(ab, bb, atc, btc);

    const int nwarps = (B / K) * C;                 // 3072 warps
    adi_kernel<<<nwarps / WARPS_PER_CTA, 32 * WARPS_PER_CTA>>>(u, out);
}